// round 12
// baseline (speedup 1.0000x reference)
#include <cuda_runtime.h>

#define N_ENT  100000
#define N_EDGE 500000
#define N_SEED 10000
#define DIM    128
#define E2     (2 * N_EDGE)

typedef unsigned long long ull;

// ---------------- scratch: one set per graph -------------------------------
__device__ __align__(16) int   g_deg[2][N_ENT];
__device__ __align__(16) int   g_off[2][N_ENT + 1];
__device__ __align__(16) int   g_cur[2][N_ENT];
__device__ __align__(16) float g_inv[2][N_ENT];
__device__ __align__(16) float g_selfw[2][N_ENT];
__device__ __align__(16) int2  g_adj[2][E2];          // {nbr, w_bits}
__device__ __align__(16) float g_z[2][N_ENT * DIM];
__device__ __align__(16) float g_x1[2][N_ENT * DIM];
__device__ __align__(16) int   g_bsum[2][256];
__device__ __align__(16) int   g_bpref[2][256];

// ---------------- f32x2 packed-FMA helpers (sm_10x) -------------------------
__device__ __forceinline__ ull pack2(float a, float b) {
    ull r;
    asm("mov.b64 %0, {%1, %2};" : "=l"(r) : "f"(a), "f"(b));
    return r;
}
__device__ __forceinline__ ull fma2(ull a, ull b, ull c) {
    ull d;
    asm("fma.rn.f32x2 %0, %1, %2, %3;" : "=l"(d) : "l"(a), "l"(b), "l"(c));
    return d;
}
__device__ __forceinline__ void unpack2(ull v, float& lo, float& hi) {
    asm("mov.b64 {%0, %1}, %2;" : "=f"(lo), "=f"(hi) : "l"(v));
}

// ---------------- CSR build ------------------------------------------------
__global__ void k_zero_deg(int g) {
    int i = blockIdx.x * 256 + threadIdx.x;
    if (i < N_ENT) g_deg[g][i] = 0;
}

__global__ void k_count(const int* __restrict__ edges, int g) {
    int i = blockIdx.x * 256 + threadIdx.x;
    if (i < N_EDGE) {
        int2 e = ((const int2*)edges)[i];
        atomicAdd(&g_deg[g][e.x], 1);
        atomicAdd(&g_deg[g][e.y], 1);
    }
}

__global__ void k_scan_a(int g) {
    __shared__ int s[512];
    int b = blockIdx.x, tid = threadIdx.x;
    int i = b * 512 + tid;
    int v = (i < N_ENT) ? g_deg[g][i] : 0;
    s[tid] = v;
    __syncthreads();
    #pragma unroll
    for (int d = 1; d < 512; d <<= 1) {
        int t = (tid >= d) ? s[tid - d] : 0;
        __syncthreads();
        s[tid] += t;
        __syncthreads();
    }
    if (i < N_ENT) g_off[g][i + 1] = s[tid];
    if (tid == 511) g_bsum[g][b] = s[511];
}

__global__ void k_scan_b(int nb, int g) {
    __shared__ int s[256];
    int tid = threadIdx.x;
    int v = (tid < nb) ? g_bsum[g][tid] : 0;
    s[tid] = v;
    __syncthreads();
    #pragma unroll
    for (int d = 1; d < 256; d <<= 1) {
        int t = (tid >= d) ? s[tid - d] : 0;
        __syncthreads();
        s[tid] += t;
        __syncthreads();
    }
    if (tid < nb) g_bpref[g][tid] = s[tid] - v;
}

__global__ void k_scan_c(int g) {
    int i = blockIdx.x * 256 + threadIdx.x;
    if (i < N_ENT) {
        int inc = g_off[g][i + 1] + g_bpref[g][i / 512];
        g_off[g][i + 1] = inc;
        g_cur[g][i] = inc - g_deg[g][i];
        float d = (float)(g_deg[g][i] + 1);   // +1 self loop
        g_inv[g][i] = rsqrtf(d);
        g_selfw[g][i] = 1.0f / d;
    }
    if (i == 0) g_off[g][0] = 0;
}

__global__ void k_fill(const int* __restrict__ edges, int g) {
    int i = blockIdx.x * 256 + threadIdx.x;
    if (i < N_EDGE) {
        int2 e = ((const int2*)edges)[i];
        float w = g_inv[g][e.x] * g_inv[g][e.y];
        int wb = __float_as_int(w);
        int p = atomicAdd(&g_cur[g][e.x], 1);
        g_adj[g][p] = make_int2(e.y, wb);
        p = atomicAdd(&g_cur[g][e.y], 1);
        g_adj[g][p] = make_int2(e.x, wb);
    }
}

// ---------------- GEMM: Z = X @ W  (M=100000, N=K=128), reg-blocked f32x2 ---
#define BK 16

__global__ __launch_bounds__(128, 2)
void k_gemm(const float* __restrict__ X,
            const float* __restrict__ W,
            float* __restrict__ Z) {
    __shared__ __align__(16) float As[2][BK * 128];
    __shared__ __align__(16) float Bs[2][BK * 128];

    const int t  = threadIdx.x;
    const int tx = t & 15;          // col group: cols tx*8..+8
    const int ty = t >> 4;          // row group: rows ty*16..+16
    const int rowBase = blockIdx.x * 128;

    const int arow = t >> 2;        // + 32*i
    const int ak4  = t & 3;
    const int bk0  = t >> 5;        // + 4*i
    const int bc4  = t & 31;

    float4 aReg[4], bReg[4];

    {
        #pragma unroll
        for (int i = 0; i < 4; i++) {
            int gr = rowBase + arow + 32 * i;
            if (gr >= N_ENT) gr = N_ENT - 1;            // clamp (stores guarded)
            aReg[i] = __ldg((const float4*)(X + (size_t)gr * DIM + ak4 * 4));
            bReg[i] = __ldg((const float4*)(W + (size_t)(bk0 + 4 * i) * DIM + bc4 * 4));
        }
        #pragma unroll
        for (int i = 0; i < 4; i++) {
            float* a = As[0] + (ak4 * 4) * 128 + arow + 32 * i;   // As[k][row]
            a[0] = aReg[i].x; a[128] = aReg[i].y;
            a[256] = aReg[i].z; a[384] = aReg[i].w;
            *(float4*)(Bs[0] + (bk0 + 4 * i) * 128 + bc4 * 4) = bReg[i];
        }
    }
    __syncthreads();

    ull acc[8][8];
    #pragma unroll
    for (int r = 0; r < 8; r++)
        #pragma unroll
        for (int c = 0; c < 8; c++) acc[r][c] = 0ull;

    #pragma unroll
    for (int kc = 0; kc < 8; kc++) {
        int buf = kc & 1;
        if (kc < 7) {
            int kOff = (kc + 1) * BK;
            #pragma unroll
            for (int i = 0; i < 4; i++) {
                int gr = rowBase + arow + 32 * i;
                if (gr >= N_ENT) gr = N_ENT - 1;
                aReg[i] = __ldg((const float4*)(X + (size_t)gr * DIM + kOff + ak4 * 4));
                bReg[i] = __ldg((const float4*)(W + (size_t)(kOff + bk0 + 4 * i) * DIM + bc4 * 4));
            }
        }
        #pragma unroll
        for (int k = 0; k < BK; k++) {
            ull ap[8];
            const ulonglong2* arowp =
                (const ulonglong2*)(As[buf] + k * 128 + ty * 16);
            #pragma unroll
            for (int i = 0; i < 4; i++) {
                ulonglong2 v = arowp[i];
                ap[2 * i] = v.x; ap[2 * i + 1] = v.y;
            }
            float4 b0 = *(const float4*)(Bs[buf] + k * 128 + tx * 8);
            float4 b1 = *(const float4*)(Bs[buf] + k * 128 + tx * 8 + 4);
            ull bb[8];
            bb[0] = pack2(b0.x, b0.x); bb[1] = pack2(b0.y, b0.y);
            bb[2] = pack2(b0.z, b0.z); bb[3] = pack2(b0.w, b0.w);
            bb[4] = pack2(b1.x, b1.x); bb[5] = pack2(b1.y, b1.y);
            bb[6] = pack2(b1.z, b1.z); bb[7] = pack2(b1.w, b1.w);
            #pragma unroll
            for (int c = 0; c < 8; c++)
                #pragma unroll
                for (int rp = 0; rp < 8; rp++)
                    acc[rp][c] = fma2(ap[rp], bb[c], acc[rp][c]);
        }
        if (kc < 7) {
            int nb = buf ^ 1;
            #pragma unroll
            for (int i = 0; i < 4; i++) {
                float* a = As[nb] + (ak4 * 4) * 128 + arow + 32 * i;
                a[0] = aReg[i].x; a[128] = aReg[i].y;
                a[256] = aReg[i].z; a[384] = aReg[i].w;
                *(float4*)(Bs[nb] + (bk0 + 4 * i) * 128 + bc4 * 4) = bReg[i];
            }
            __syncthreads();
        }
    }

    #pragma unroll
    for (int rp = 0; rp < 8; rp++) {
        int r0 = rowBase + ty * 16 + 2 * rp;
        float lo[8], hi[8];
        #pragma unroll
        for (int c = 0; c < 8; c++) unpack2(acc[rp][c], lo[c], hi[c]);
        if (r0 < N_ENT) {
            float4* zr = (float4*)(Z + (size_t)r0 * DIM + tx * 8);
            zr[0] = make_float4(lo[0], lo[1], lo[2], lo[3]);
            zr[1] = make_float4(lo[4], lo[5], lo[6], lo[7]);
        }
        if (r0 + 1 < N_ENT) {
            float4* zr = (float4*)(Z + (size_t)(r0 + 1) * DIM + tx * 8);
            zr[0] = make_float4(hi[0], hi[1], hi[2], hi[3]);
            zr[1] = make_float4(hi[4], hi[5], hi[6], hi[7]);
        }
    }
}

// ---------------- aggregation: Xout[v] = relu(selfw*Z[v] + sum w*Z[u] + Xin[v])
__global__ void k_agg(const float* __restrict__ Z,
                      const float* __restrict__ Xin,
                      float* __restrict__ Xout, int g) {
    int warp = threadIdx.x >> 5;
    int lane = threadIdx.x & 31;
    int v = blockIdx.x * 8 + warp;
    if (v >= N_ENT) return;

    const float4* z4 = (const float4*)Z;
    float sw = g_selfw[g][v];
    float4 zv = __ldg(&z4[v * 32 + lane]);
    float4 acc = make_float4(zv.x * sw, zv.y * sw, zv.z * sw, zv.w * sw);

    const int2* __restrict__ adj = g_adj[g];
    int s = g_off[g][v], e = g_off[g][v + 1];
    int i = s;
    for (; i + 3 < e; i += 4) {
        int2 e0 = __ldg(&adj[i]);
        int2 e1 = __ldg(&adj[i + 1]);
        int2 e2 = __ldg(&adj[i + 2]);
        int2 e3 = __ldg(&adj[i + 3]);
        float w0 = __int_as_float(e0.y), w1 = __int_as_float(e1.y);
        float w2 = __int_as_float(e2.y), w3 = __int_as_float(e3.y);
        float4 a0 = __ldg(&z4[e0.x * 32 + lane]);
        float4 a1 = __ldg(&z4[e1.x * 32 + lane]);
        float4 a2 = __ldg(&z4[e2.x * 32 + lane]);
        float4 a3 = __ldg(&z4[e3.x * 32 + lane]);
        acc.x = fmaf(a0.x, w0, acc.x); acc.y = fmaf(a0.y, w0, acc.y);
        acc.z = fmaf(a0.z, w0, acc.z); acc.w = fmaf(a0.w, w0, acc.w);
        acc.x = fmaf(a1.x, w1, acc.x); acc.y = fmaf(a1.y, w1, acc.y);
        acc.z = fmaf(a1.z, w1, acc.z); acc.w = fmaf(a1.w, w1, acc.w);
        acc.x = fmaf(a2.x, w2, acc.x); acc.y = fmaf(a2.y, w2, acc.y);
        acc.z = fmaf(a2.z, w2, acc.z); acc.w = fmaf(a2.w, w2, acc.w);
        acc.x = fmaf(a3.x, w3, acc.x); acc.y = fmaf(a3.y, w3, acc.y);
        acc.z = fmaf(a3.z, w3, acc.z); acc.w = fmaf(a3.w, w3, acc.w);
    }
    for (; i < e; i++) {
        int2 e0 = __ldg(&adj[i]);
        float w = __int_as_float(e0.y);
        float4 a0 = __ldg(&z4[e0.x * 32 + lane]);
        acc.x = fmaf(a0.x, w, acc.x); acc.y = fmaf(a0.y, w, acc.y);
        acc.z = fmaf(a0.z, w, acc.z); acc.w = fmaf(a0.w, w, acc.w);
    }

    float4 xi = __ldg(&((const float4*)Xin)[v * 32 + lane]);
    float4 r;
    r.x = fmaxf(acc.x + xi.x, 0.0f);
    r.y = fmaxf(acc.y + xi.y, 0.0f);
    r.z = fmaxf(acc.z + xi.z, 0.0f);
    r.w = fmaxf(acc.w + xi.w, 0.0f);
    ((float4*)Xout)[v * 32 + lane] = r;
}

// ---------------- seed gather ----------------------------------------------
__global__ void k_gather(const int* __restrict__ seeds,
                         const float* __restrict__ ent,
                         float* __restrict__ out) {
    int i = blockIdx.x * 256 + threadIdx.x;
    if (i < N_SEED * 32) {
        int s = i >> 5, q = i & 31;
        ((float4*)out)[i] = __ldg(&((const float4*)ent)[seeds[s] * 32 + q]);
    }
}

// ---------------- driver ----------------------------------------------------
static void build_csr(const int* edges, int g, cudaStream_t st) {
    const int GB_ENT = (N_ENT + 255) / 256;
    const int GB_EDGE = (N_EDGE + 255) / 256;
    const int NB_SCAN = (N_ENT + 511) / 512;
    k_zero_deg<<<GB_ENT, 256, 0, st>>>(g);
    k_count<<<GB_EDGE, 256, 0, st>>>(edges, g);
    k_scan_a<<<NB_SCAN, 512, 0, st>>>(g);
    k_scan_b<<<1, 256, 0, st>>>(NB_SCAN, g);
    k_scan_c<<<GB_ENT, 256, 0, st>>>(g);
    k_fill<<<GB_EDGE, 256, 0, st>>>(edges, g);
}

static void run_compute(const float* emb, const float* W2,
                        const int* seeds, float* o_ent, float* o_seed,
                        float* z, float* x1, int g, cudaStream_t st) {
    const int GEMM_GRID = (N_ENT + 127) / 128;
    const int AGG_GRID = (N_ENT + 7) / 8;
    // layer-1 GEMM already issued on st; CSR joined before this point
    k_agg<<<AGG_GRID, 256, 0, st>>>(z, emb, x1, g);
    k_gemm<<<GEMM_GRID, 128, 0, st>>>(x1, W2, z);
    k_agg<<<AGG_GRID, 256, 0, st>>>(z, x1, o_ent, g);
    k_gather<<<(N_SEED * 32 + 255) / 256, 256, 0, st>>>(seeds, o_ent, o_seed);
}

extern "C" void kernel_launch(void* const* d_in, const int* in_sizes, int n_in,
                              void* d_out, int out_size) {
    const int*   sr_seeds = (const int*)d_in[0];
    const int*   tg_seeds = (const int*)d_in[1];
    const float* emb_sr   = (const float*)d_in[4];
    const float* emb_tg   = (const float*)d_in[5];
    const int*   edges_sr = (const int*)d_in[6];
    const int*   edges_tg = (const int*)d_in[7];
    const float* W1       = (const float*)d_in[8];
    const float* W2       = (const float*)d_in[9];

    float* out = (float*)d_out;
    float* o_sr_seed = out;
    float* o_tg_seed = out + (size_t)N_SEED * DIM;
    float* o_sr_ent  = out + (size_t)2 * N_SEED * DIM;
    float* o_tg_ent  = o_sr_ent + (size_t)N_ENT * DIM;

    float* zbase;  cudaGetSymbolAddress((void**)&zbase, g_z);
    float* x1base; cudaGetSymbolAddress((void**)&x1base, g_x1);
    float* z_sr = zbase,  *z_tg = zbase + (size_t)N_ENT * DIM;
    float* x1_sr = x1base, *x1_tg = x1base + (size_t)N_ENT * DIM;

    // side streams + events, created once (first call is outside capture)
    static cudaStream_t s_tg = nullptr, s_csr = nullptr;
    static cudaEvent_t ev_fork = nullptr, ev_csr0 = nullptr, ev_csr1 = nullptr,
                       ev_join = nullptr;
    if (!s_tg) {
        cudaStreamCreateWithFlags(&s_tg, cudaStreamNonBlocking);
        cudaStreamCreateWithFlags(&s_csr, cudaStreamNonBlocking);
        cudaEventCreateWithFlags(&ev_fork, cudaEventDisableTiming);
        cudaEventCreateWithFlags(&ev_csr0, cudaEventDisableTiming);
        cudaEventCreateWithFlags(&ev_csr1, cudaEventDisableTiming);
        cudaEventCreateWithFlags(&ev_join, cudaEventDisableTiming);
    }

    const int GEMM_GRID = (N_ENT + 127) / 128;

    // fork from capture stream
    cudaEventRecord(ev_fork, 0);
    cudaStreamWaitEvent(s_tg, ev_fork, 0);
    cudaStreamWaitEvent(s_csr, ev_fork, 0);

    // both CSR builds sequentially on one dedicated stream
    build_csr(edges_sr, 0, s_csr);
    cudaEventRecord(ev_csr0, s_csr);
    build_csr(edges_tg, 1, s_csr);
    cudaEventRecord(ev_csr1, s_csr);

    // layer-1 GEMMs (independent of CSR) overlap with the CSR chain
    k_gemm<<<GEMM_GRID, 128, 0, 0>>>(emb_sr, W1, z_sr);
    k_gemm<<<GEMM_GRID, 128, 0, s_tg>>>(emb_tg, W1, z_tg);

    // join CSR before aggregation on each compute stream
    cudaStreamWaitEvent(0, ev_csr0, 0);
    cudaStreamWaitEvent(s_tg, ev_csr1, 0);

    run_compute(emb_sr, W2, sr_seeds, o_sr_ent, o_sr_seed,
                z_sr, x1_sr, 0, 0);
    run_compute(emb_tg, W2, tg_seeds, o_tg_ent, o_tg_seed,
                z_tg, x1_tg, 1, s_tg);

    // join tg into capture stream
    cudaEventRecord(ev_join, s_tg);
    cudaStreamWaitEvent(0, ev_join, 0);
}

// round 14
// speedup vs baseline: 1.0064x; 1.0064x over previous
#include <cuda_runtime.h>

#define N_ENT  100000
#define N_EDGE 500000
#define N_SEED 10000
#define DIM    128
#define E2     (2 * N_EDGE)

typedef unsigned long long ull;

// ---------------- scratch: one set per graph -------------------------------
__device__ __align__(16) int   g_deg[2][N_ENT];
__device__ __align__(16) int   g_off[2][N_ENT + 1];
__device__ __align__(16) int   g_cur[2][N_ENT];
__device__ __align__(16) float g_inv[2][N_ENT];
__device__ __align__(16) float g_selfw[2][N_ENT];
__device__ __align__(16) int2  g_adj[2][E2];          // {nbr, w_bits}
__device__ __align__(16) float g_z[2][N_ENT * DIM];
__device__ __align__(16) float g_x1[2][N_ENT * DIM];
__device__ __align__(16) int   g_bsum[2][256];
__device__ __align__(16) int   g_bpref[2][256];

// ---------------- f32x2 packed-FMA helpers (sm_10x) -------------------------
__device__ __forceinline__ ull pack2(float a, float b) {
    ull r;
    asm("mov.b64 %0, {%1, %2};" : "=l"(r) : "f"(a), "f"(b));
    return r;
}
__device__ __forceinline__ ull fma2(ull a, ull b, ull c) {
    ull d;
    asm("fma.rn.f32x2 %0, %1, %2, %3;" : "=l"(d) : "l"(a), "l"(b), "l"(c));
    return d;
}
__device__ __forceinline__ void unpack2(ull v, float& lo, float& hi) {
    asm("mov.b64 {%0, %1}, %2;" : "=f"(lo), "=f"(hi) : "l"(v));
}

// ---------------- CSR build ------------------------------------------------
__global__ void k_zero_deg(int g) {
    int i = blockIdx.x * 256 + threadIdx.x;
    if (i < N_ENT) g_deg[g][i] = 0;
}

__global__ void k_count(const int* __restrict__ edges, int g) {
    int i = blockIdx.x * 256 + threadIdx.x;
    if (i < N_EDGE) {
        int2 e = ((const int2*)edges)[i];
        atomicAdd(&g_deg[g][e.x], 1);
        atomicAdd(&g_deg[g][e.y], 1);
    }
}

__global__ void k_scan_a(int g) {
    __shared__ int s[512];
    int b = blockIdx.x, tid = threadIdx.x;
    int i = b * 512 + tid;
    int v = (i < N_ENT) ? g_deg[g][i] : 0;
    s[tid] = v;
    __syncthreads();
    #pragma unroll
    for (int d = 1; d < 512; d <<= 1) {
        int t = (tid >= d) ? s[tid - d] : 0;
        __syncthreads();
        s[tid] += t;
        __syncthreads();
    }
    if (i < N_ENT) g_off[g][i + 1] = s[tid];
    if (tid == 511) g_bsum[g][b] = s[511];
}

__global__ void k_scan_b(int nb, int g) {
    __shared__ int s[256];
    int tid = threadIdx.x;
    int v = (tid < nb) ? g_bsum[g][tid] : 0;
    s[tid] = v;
    __syncthreads();
    #pragma unroll
    for (int d = 1; d < 256; d <<= 1) {
        int t = (tid >= d) ? s[tid - d] : 0;
        __syncthreads();
        s[tid] += t;
        __syncthreads();
    }
    if (tid < nb) g_bpref[g][tid] = s[tid] - v;
}

__global__ void k_scan_c(int g) {
    int i = blockIdx.x * 256 + threadIdx.x;
    if (i < N_ENT) {
        int inc = g_off[g][i + 1] + g_bpref[g][i / 512];
        g_off[g][i + 1] = inc;
        g_cur[g][i] = inc - g_deg[g][i];
        float d = (float)(g_deg[g][i] + 1);   // +1 self loop
        g_inv[g][i] = rsqrtf(d);
        g_selfw[g][i] = 1.0f / d;
    }
    if (i == 0) g_off[g][0] = 0;
}

__global__ void k_fill(const int* __restrict__ edges, int g) {
    int i = blockIdx.x * 256 + threadIdx.x;
    if (i < N_EDGE) {
        int2 e = ((const int2*)edges)[i];
        float w = g_inv[g][e.x] * g_inv[g][e.y];
        int wb = __float_as_int(w);
        int p = atomicAdd(&g_cur[g][e.x], 1);
        g_adj[g][p] = make_int2(e.y, wb);
        p = atomicAdd(&g_cur[g][e.y], 1);
        g_adj[g][p] = make_int2(e.x, wb);
    }
}

// ---------------- GEMM: Z = X @ W  (M=100000, N=K=128), reg-blocked f32x2 ---
#define BK 16

__global__ __launch_bounds__(128, 2)
void k_gemm(const float* __restrict__ X,
            const float* __restrict__ W,
            float* __restrict__ Z) {
    __shared__ __align__(16) float As[2][BK * 128];
    __shared__ __align__(16) float Bs[2][BK * 128];

    const int t  = threadIdx.x;
    const int tx = t & 15;          // col group: cols tx*8..+8
    const int ty = t >> 4;          // row group: rows ty*16..+16
    const int rowBase = blockIdx.x * 128;

    const int arow = t >> 2;        // + 32*i
    const int ak4  = t & 3;
    const int bk0  = t >> 5;        // + 4*i
    const int bc4  = t & 31;

    float4 aReg[4], bReg[4];

    {
        #pragma unroll
        for (int i = 0; i < 4; i++) {
            int gr = rowBase + arow + 32 * i;
            if (gr >= N_ENT) gr = N_ENT - 1;            // clamp (stores guarded)
            aReg[i] = __ldg((const float4*)(X + (size_t)gr * DIM + ak4 * 4));
            bReg[i] = __ldg((const float4*)(W + (size_t)(bk0 + 4 * i) * DIM + bc4 * 4));
        }
        #pragma unroll
        for (int i = 0; i < 4; i++) {
            float* a = As[0] + (ak4 * 4) * 128 + arow + 32 * i;   // As[k][row]
            a[0] = aReg[i].x; a[128] = aReg[i].y;
            a[256] = aReg[i].z; a[384] = aReg[i].w;
            *(float4*)(Bs[0] + (bk0 + 4 * i) * 128 + bc4 * 4) = bReg[i];
        }
    }
    __syncthreads();

    ull acc[8][8];
    #pragma unroll
    for (int r = 0; r < 8; r++)
        #pragma unroll
        for (int c = 0; c < 8; c++) acc[r][c] = 0ull;

    #pragma unroll
    for (int kc = 0; kc < 8; kc++) {
        int buf = kc & 1;
        if (kc < 7) {
            int kOff = (kc + 1) * BK;
            #pragma unroll
            for (int i = 0; i < 4; i++) {
                int gr = rowBase + arow + 32 * i;
                if (gr >= N_ENT) gr = N_ENT - 1;
                aReg[i] = __ldg((const float4*)(X + (size_t)gr * DIM + kOff + ak4 * 4));
                bReg[i] = __ldg((const float4*)(W + (size_t)(kOff + bk0 + 4 * i) * DIM + bc4 * 4));
            }
        }
        #pragma unroll
        for (int k = 0; k < BK; k++) {
            ull ap[8];
            const ulonglong2* arowp =
                (const ulonglong2*)(As[buf] + k * 128 + ty * 16);
            #pragma unroll
            for (int i = 0; i < 4; i++) {
                ulonglong2 v = arowp[i];
                ap[2 * i] = v.x; ap[2 * i + 1] = v.y;
            }
            float4 b0 = *(const float4*)(Bs[buf] + k * 128 + tx * 8);
            float4 b1 = *(const float4*)(Bs[buf] + k * 128 + tx * 8 + 4);
            ull bb[8];
            bb[0] = pack2(b0.x, b0.x); bb[1] = pack2(b0.y, b0.y);
            bb[2] = pack2(b0.z, b0.z); bb[3] = pack2(b0.w, b0.w);
            bb[4] = pack2(b1.x, b1.x); bb[5] = pack2(b1.y, b1.y);
            bb[6] = pack2(b1.z, b1.z); bb[7] = pack2(b1.w, b1.w);
            #pragma unroll
            for (int c = 0; c < 8; c++)
                #pragma unroll
                for (int rp = 0; rp < 8; rp++)
                    acc[rp][c] = fma2(ap[rp], bb[c], acc[rp][c]);
        }
        if (kc < 7) {
            int nb = buf ^ 1;
            #pragma unroll
            for (int i = 0; i < 4; i++) {
                float* a = As[nb] + (ak4 * 4) * 128 + arow + 32 * i;
                a[0] = aReg[i].x; a[128] = aReg[i].y;
                a[256] = aReg[i].z; a[384] = aReg[i].w;
                *(float4*)(Bs[nb] + (bk0 + 4 * i) * 128 + bc4 * 4) = bReg[i];
            }
            __syncthreads();
        }
    }

    #pragma unroll
    for (int rp = 0; rp < 8; rp++) {
        int r0 = rowBase + ty * 16 + 2 * rp;
        float lo[8], hi[8];
        #pragma unroll
        for (int c = 0; c < 8; c++) unpack2(acc[rp][c], lo[c], hi[c]);
        if (r0 < N_ENT) {
            float4* zr = (float4*)(Z + (size_t)r0 * DIM + tx * 8);
            zr[0] = make_float4(lo[0], lo[1], lo[2], lo[3]);
            zr[1] = make_float4(lo[4], lo[5], lo[6], lo[7]);
        }
        if (r0 + 1 < N_ENT) {
            float4* zr = (float4*)(Z + (size_t)(r0 + 1) * DIM + tx * 8);
            zr[0] = make_float4(hi[0], hi[1], hi[2], hi[3]);
            zr[1] = make_float4(hi[4], hi[5], hi[6], hi[7]);
        }
    }
}

// ---------------- aggregation: Xout[v] = relu(selfw*Z[v] + sum w*Z[u] + Xin[v])
__global__ void k_agg(const float* __restrict__ Z,
                      const float* __restrict__ Xin,
                      float* __restrict__ Xout, int g) {
    int warp = threadIdx.x >> 5;
    int lane = threadIdx.x & 31;
    int v = blockIdx.x * 8 + warp;
    if (v >= N_ENT) return;

    const float4* z4 = (const float4*)Z;
    float sw = g_selfw[g][v];
    float4 zv = __ldg(&z4[v * 32 + lane]);
    float4 acc = make_float4(zv.x * sw, zv.y * sw, zv.z * sw, zv.w * sw);

    const int2* __restrict__ adj = g_adj[g];
    int s = g_off[g][v], e = g_off[g][v + 1];
    int i = s;
    for (; i + 3 < e; i += 4) {
        int2 e0 = __ldg(&adj[i]);
        int2 e1 = __ldg(&adj[i + 1]);
        int2 e2 = __ldg(&adj[i + 2]);
        int2 e3 = __ldg(&adj[i + 3]);
        float w0 = __int_as_float(e0.y), w1 = __int_as_float(e1.y);
        float w2 = __int_as_float(e2.y), w3 = __int_as_float(e3.y);
        float4 a0 = __ldg(&z4[e0.x * 32 + lane]);
        float4 a1 = __ldg(&z4[e1.x * 32 + lane]);
        float4 a2 = __ldg(&z4[e2.x * 32 + lane]);
        float4 a3 = __ldg(&z4[e3.x * 32 + lane]);
        acc.x = fmaf(a0.x, w0, acc.x); acc.y = fmaf(a0.y, w0, acc.y);
        acc.z = fmaf(a0.z, w0, acc.z); acc.w = fmaf(a0.w, w0, acc.w);
        acc.x = fmaf(a1.x, w1, acc.x); acc.y = fmaf(a1.y, w1, acc.y);
        acc.z = fmaf(a1.z, w1, acc.z); acc.w = fmaf(a1.w, w1, acc.w);
        acc.x = fmaf(a2.x, w2, acc.x); acc.y = fmaf(a2.y, w2, acc.y);
        acc.z = fmaf(a2.z, w2, acc.z); acc.w = fmaf(a2.w, w2, acc.w);
        acc.x = fmaf(a3.x, w3, acc.x); acc.y = fmaf(a3.y, w3, acc.y);
        acc.z = fmaf(a3.z, w3, acc.z); acc.w = fmaf(a3.w, w3, acc.w);
    }
    for (; i < e; i++) {
        int2 e0 = __ldg(&adj[i]);
        float w = __int_as_float(e0.y);
        float4 a0 = __ldg(&z4[e0.x * 32 + lane]);
        acc.x = fmaf(a0.x, w, acc.x); acc.y = fmaf(a0.y, w, acc.y);
        acc.z = fmaf(a0.z, w, acc.z); acc.w = fmaf(a0.w, w, acc.w);
    }

    float4 xi = __ldg(&((const float4*)Xin)[v * 32 + lane]);
    float4 r;
    r.x = fmaxf(acc.x + xi.x, 0.0f);
    r.y = fmaxf(acc.y + xi.y, 0.0f);
    r.z = fmaxf(acc.z + xi.z, 0.0f);
    r.w = fmaxf(acc.w + xi.w, 0.0f);
    ((float4*)Xout)[v * 32 + lane] = r;
}

// ---------------- seed gather ----------------------------------------------
__global__ void k_gather(const int* __restrict__ seeds,
                         const float* __restrict__ ent,
                         float* __restrict__ out) {
    int i = blockIdx.x * 256 + threadIdx.x;
    if (i < N_SEED * 32) {
        int s = i >> 5, q = i & 31;
        ((float4*)out)[i] = __ldg(&((const float4*)ent)[seeds[s] * 32 + q]);
    }
}

// ---------------- driver ----------------------------------------------------
static void build_csr(const int* edges, int g, cudaStream_t st) {
    const int GB_ENT = (N_ENT + 255) / 256;
    const int GB_EDGE = (N_EDGE + 255) / 256;
    const int NB_SCAN = (N_ENT + 511) / 512;
    k_zero_deg<<<GB_ENT, 256, 0, st>>>(g);
    k_count<<<GB_EDGE, 256, 0, st>>>(edges, g);
    k_scan_a<<<NB_SCAN, 512, 0, st>>>(g);
    k_scan_b<<<1, 256, 0, st>>>(NB_SCAN, g);
    k_scan_c<<<GB_ENT, 256, 0, st>>>(g);
    k_fill<<<GB_EDGE, 256, 0, st>>>(edges, g);
}

extern "C" void kernel_launch(void* const* d_in, const int* in_sizes, int n_in,
                              void* d_out, int out_size) {
    const int*   sr_seeds = (const int*)d_in[0];
    const int*   tg_seeds = (const int*)d_in[1];
    const float* emb_sr   = (const float*)d_in[4];
    const float* emb_tg   = (const float*)d_in[5];
    const int*   edges_sr = (const int*)d_in[6];
    const int*   edges_tg = (const int*)d_in[7];
    const float* W1       = (const float*)d_in[8];
    const float* W2       = (const float*)d_in[9];

    float* out = (float*)d_out;
    float* o_sr_seed = out;
    float* o_tg_seed = out + (size_t)N_SEED * DIM;
    float* o_sr_ent  = out + (size_t)2 * N_SEED * DIM;
    float* o_tg_ent  = o_sr_ent + (size_t)N_ENT * DIM;

    float* zbase;  cudaGetSymbolAddress((void**)&zbase, g_z);
    float* x1base; cudaGetSymbolAddress((void**)&x1base, g_x1);
    float* z_sr = zbase,  *z_tg = zbase + (size_t)N_ENT * DIM;
    float* x1_sr = x1base, *x1_tg = x1base + (size_t)N_ENT * DIM;

    // side streams + events, created once (first call is outside capture)
    static cudaStream_t s_tg = nullptr, s_csr = nullptr;
    static cudaEvent_t ev_fork = nullptr, ev_csr0 = nullptr, ev_join = nullptr;
    if (!s_tg) {
        cudaStreamCreateWithFlags(&s_tg, cudaStreamNonBlocking);
        cudaStreamCreateWithFlags(&s_csr, cudaStreamNonBlocking);
        cudaEventCreateWithFlags(&ev_fork, cudaEventDisableTiming);
        cudaEventCreateWithFlags(&ev_csr0, cudaEventDisableTiming);
        cudaEventCreateWithFlags(&ev_join, cudaEventDisableTiming);
    }

    const int GEMM_GRID = (N_ENT + 127) / 128;
    const int AGG_GRID  = (N_ENT + 7) / 8;
    const int GATHER_GRID = (N_SEED * 32 + 255) / 256;

    // fork from capture stream
    cudaEventRecord(ev_fork, 0);
    cudaStreamWaitEvent(s_tg, ev_fork, 0);
    cudaStreamWaitEvent(s_csr, ev_fork, 0);

    // sr CSR on dedicated stream (hidden under sr's layer-1 GEMM)
    build_csr(edges_sr, 0, s_csr);
    cudaEventRecord(ev_csr0, s_csr);

    // tg: CSR inline first — acts as one-stage pipeline skew so tg's GEMM
    // phases overlap sr's AGG phases (keeps one z tile L2-resident at a time)
    build_csr(edges_tg, 1, s_tg);

    // sr pipeline on capture stream
    k_gemm<<<GEMM_GRID, 128, 0, 0>>>(emb_sr, W1, z_sr);
    cudaStreamWaitEvent(0, ev_csr0, 0);
    k_agg<<<AGG_GRID, 256, 0, 0>>>(z_sr, emb_sr, x1_sr, 0);
    k_gemm<<<GEMM_GRID, 128, 0, 0>>>(x1_sr, W2, z_sr);
    k_agg<<<AGG_GRID, 256, 0, 0>>>(z_sr, x1_sr, o_sr_ent, 0);
    k_gather<<<GATHER_GRID, 256, 0, 0>>>(sr_seeds, o_sr_ent, o_sr_seed);

    // tg pipeline on s_tg (skewed by its CSR chain)
    k_gemm<<<GEMM_GRID, 128, 0, s_tg>>>(emb_tg, W1, z_tg);
    k_agg<<<AGG_GRID, 256, 0, s_tg>>>(z_tg, emb_tg, x1_tg, 1);
    k_gemm<<<GEMM_GRID, 128, 0, s_tg>>>(x1_tg, W2, z_tg);
    k_agg<<<AGG_GRID, 256, 0, s_tg>>>(z_tg, x1_tg, o_tg_ent, 1);
    k_gather<<<GATHER_GRID, 256, 0, s_tg>>>(tg_seeds, o_tg_ent, o_tg_seed);

    // join tg into capture stream
    cudaEventRecord(ev_join, s_tg);
    cudaStreamWaitEvent(0, ev_join, 0);
}

// round 16
// speedup vs baseline: 1.1661x; 1.1587x over previous
#include <cuda_runtime.h>
#include <cuda_fp16.h>

#define N_ENT  100000
#define N_EDGE 500000
#define N_SEED 10000
#define DIM    128
#define E2     (2 * N_EDGE)

typedef unsigned long long ull;

// ---------------- scratch: one set per graph -------------------------------
__device__ __align__(16) int    g_deg[2][N_ENT];
__device__ __align__(16) int    g_off[2][N_ENT + 1];
__device__ __align__(16) int    g_cur[2][N_ENT];
__device__ __align__(16) float  g_inv[2][N_ENT];
__device__ __align__(16) float  g_selfw[2][N_ENT];
__device__ __align__(16) int2   g_adj[2][E2];           // {nbr, w_bits}
__device__ __align__(16) __half g_zh[2][N_ENT * DIM];   // fp16 z = X@W
__device__ __align__(16) float  g_x1[2][N_ENT * DIM];
__device__ __align__(16) int    g_bsum[2][256];
__device__ __align__(16) int    g_bpref[2][256];

// ---------------- f32x2 packed-FMA helpers (sm_10x) -------------------------
__device__ __forceinline__ ull pack2(float a, float b) {
    ull r;
    asm("mov.b64 %0, {%1, %2};" : "=l"(r) : "f"(a), "f"(b));
    return r;
}
__device__ __forceinline__ ull fma2(ull a, ull b, ull c) {
    ull d;
    asm("fma.rn.f32x2 %0, %1, %2, %3;" : "=l"(d) : "l"(a), "l"(b), "l"(c));
    return d;
}
__device__ __forceinline__ void unpack2(ull v, float& lo, float& hi) {
    asm("mov.b64 {%0, %1}, %2;" : "=f"(lo), "=f"(hi) : "l"(v));
}

// ---------------- CSR build ------------------------------------------------
__global__ void k_zero_deg(int g) {
    int i = blockIdx.x * 256 + threadIdx.x;
    if (i < N_ENT) g_deg[g][i] = 0;
}

__global__ void k_count(const int* __restrict__ edges, int g) {
    int i = blockIdx.x * 256 + threadIdx.x;
    if (i < N_EDGE) {
        int2 e = ((const int2*)edges)[i];
        atomicAdd(&g_deg[g][e.x], 1);
        atomicAdd(&g_deg[g][e.y], 1);
    }
}

__global__ void k_scan_a(int g) {
    __shared__ int s[512];
    int b = blockIdx.x, tid = threadIdx.x;
    int i = b * 512 + tid;
    int v = (i < N_ENT) ? g_deg[g][i] : 0;
    s[tid] = v;
    __syncthreads();
    #pragma unroll
    for (int d = 1; d < 512; d <<= 1) {
        int t = (tid >= d) ? s[tid - d] : 0;
        __syncthreads();
        s[tid] += t;
        __syncthreads();
    }
    if (i < N_ENT) g_off[g][i + 1] = s[tid];
    if (tid == 511) g_bsum[g][b] = s[511];
}

__global__ void k_scan_b(int nb, int g) {
    __shared__ int s[256];
    int tid = threadIdx.x;
    int v = (tid < nb) ? g_bsum[g][tid] : 0;
    s[tid] = v;
    __syncthreads();
    #pragma unroll
    for (int d = 1; d < 256; d <<= 1) {
        int t = (tid >= d) ? s[tid - d] : 0;
        __syncthreads();
        s[tid] += t;
        __syncthreads();
    }
    if (tid < nb) g_bpref[g][tid] = s[tid] - v;
}

__global__ void k_scan_c(int g) {
    int i = blockIdx.x * 256 + threadIdx.x;
    if (i < N_ENT) {
        int inc = g_off[g][i + 1] + g_bpref[g][i / 512];
        g_off[g][i + 1] = inc;
        g_cur[g][i] = inc - g_deg[g][i];
        float d = (float)(g_deg[g][i] + 1);   // +1 self loop
        g_inv[g][i] = rsqrtf(d);
        g_selfw[g][i] = 1.0f / d;
    }
    if (i == 0) g_off[g][0] = 0;
}

__global__ void k_fill(const int* __restrict__ edges, int g) {
    int i = blockIdx.x * 256 + threadIdx.x;
    if (i < N_EDGE) {
        int2 e = ((const int2*)edges)[i];
        float w = g_inv[g][e.x] * g_inv[g][e.y];
        int wb = __float_as_int(w);
        int p = atomicAdd(&g_cur[g][e.x], 1);
        g_adj[g][p] = make_int2(e.y, wb);
        p = atomicAdd(&g_cur[g][e.y], 1);
        g_adj[g][p] = make_int2(e.x, wb);
    }
}

// ---------------- GEMM: Zh = fp16(X @ W)  (M=100000, N=K=128) ---------------
#define BK 16

__global__ __launch_bounds__(128, 2)
void k_gemm(const float* __restrict__ X,
            const float* __restrict__ W,
            __half* __restrict__ Zh) {
    __shared__ __align__(16) float As[2][BK * 128];
    __shared__ __align__(16) float Bs[2][BK * 128];

    const int t  = threadIdx.x;
    const int tx = t & 15;          // col group: cols tx*8..+8
    const int ty = t >> 4;          // row group: rows ty*16..+16
    const int rowBase = blockIdx.x * 128;

    const int arow = t >> 2;        // + 32*i
    const int ak4  = t & 3;
    const int bk0  = t >> 5;        // + 4*i
    const int bc4  = t & 31;

    float4 aReg[4], bReg[4];

    {
        #pragma unroll
        for (int i = 0; i < 4; i++) {
            int gr = rowBase + arow + 32 * i;
            if (gr >= N_ENT) gr = N_ENT - 1;            // clamp (stores guarded)
            aReg[i] = __ldg((const float4*)(X + (size_t)gr * DIM + ak4 * 4));
            bReg[i] = __ldg((const float4*)(W + (size_t)(bk0 + 4 * i) * DIM + bc4 * 4));
        }
        #pragma unroll
        for (int i = 0; i < 4; i++) {
            float* a = As[0] + (ak4 * 4) * 128 + arow + 32 * i;   // As[k][row]
            a[0] = aReg[i].x; a[128] = aReg[i].y;
            a[256] = aReg[i].z; a[384] = aReg[i].w;
            *(float4*)(Bs[0] + (bk0 + 4 * i) * 128 + bc4 * 4) = bReg[i];
        }
    }
    __syncthreads();

    ull acc[8][8];
    #pragma unroll
    for (int r = 0; r < 8; r++)
        #pragma unroll
        for (int c = 0; c < 8; c++) acc[r][c] = 0ull;

    #pragma unroll
    for (int kc = 0; kc < 8; kc++) {
        int buf = kc & 1;
        if (kc < 7) {
            int kOff = (kc + 1) * BK;
            #pragma unroll
            for (int i = 0; i < 4; i++) {
                int gr = rowBase + arow + 32 * i;
                if (gr >= N_ENT) gr = N_ENT - 1;
                aReg[i] = __ldg((const float4*)(X + (size_t)gr * DIM + kOff + ak4 * 4));
                bReg[i] = __ldg((const float4*)(W + (size_t)(kOff + bk0 + 4 * i) * DIM + bc4 * 4));
            }
        }
        #pragma unroll
        for (int k = 0; k < BK; k++) {
            ull ap[8];
            const ulonglong2* arowp =
                (const ulonglong2*)(As[buf] + k * 128 + ty * 16);
            #pragma unroll
            for (int i = 0; i < 4; i++) {
                ulonglong2 v = arowp[i];
                ap[2 * i] = v.x; ap[2 * i + 1] = v.y;
            }
            float4 b0 = *(const float4*)(Bs[buf] + k * 128 + tx * 8);
            float4 b1 = *(const float4*)(Bs[buf] + k * 128 + tx * 8 + 4);
            ull bb[8];
            bb[0] = pack2(b0.x, b0.x); bb[1] = pack2(b0.y, b0.y);
            bb[2] = pack2(b0.z, b0.z); bb[3] = pack2(b0.w, b0.w);
            bb[4] = pack2(b1.x, b1.x); bb[5] = pack2(b1.y, b1.y);
            bb[6] = pack2(b1.z, b1.z); bb[7] = pack2(b1.w, b1.w);
            #pragma unroll
            for (int c = 0; c < 8; c++)
                #pragma unroll
                for (int rp = 0; rp < 8; rp++)
                    acc[rp][c] = fma2(ap[rp], bb[c], acc[rp][c]);
        }
        if (kc < 7) {
            int nb = buf ^ 1;
            #pragma unroll
            for (int i = 0; i < 4; i++) {
                float* a = As[nb] + (ak4 * 4) * 128 + arow + 32 * i;
                a[0] = aReg[i].x; a[128] = aReg[i].y;
                a[256] = aReg[i].z; a[384] = aReg[i].w;
                *(float4*)(Bs[nb] + (bk0 + 4 * i) * 128 + bc4 * 4) = bReg[i];
            }
            __syncthreads();
        }
    }

    // epilogue: fp32 pairs -> half2, one STG.128 (8 cols) per row
    #pragma unroll
    for (int rp = 0; rp < 8; rp++) {
        int r0 = rowBase + ty * 16 + 2 * rp;
        float lo[8], hi[8];
        #pragma unroll
        for (int c = 0; c < 8; c++) unpack2(acc[rp][c], lo[c], hi[c]);
        if (r0 < N_ENT) {
            __half2 h[4];
            #pragma unroll
            for (int j = 0; j < 4; j++)
                h[j] = __floats2half2_rn(lo[2 * j], lo[2 * j + 1]);
            *(uint4*)(Zh + (size_t)r0 * DIM + tx * 8) = *(uint4*)h;
        }
        if (r0 + 1 < N_ENT) {
            __half2 h[4];
            #pragma unroll
            for (int j = 0; j < 4; j++)
                h[j] = __floats2half2_rn(hi[2 * j], hi[2 * j + 1]);
            *(uint4*)(Zh + (size_t)(r0 + 1) * DIM + tx * 8) = *(uint4*)h;
        }
    }
}

// ---------------- aggregation: Xout[v] = relu(selfw*Zh[v] + sum w*Zh[u] + Xin[v])
// one warp per node; lane l owns dims [4l, 4l+4) = 2 half2 = 8B gather/lane
__global__ void k_agg(const __half* __restrict__ Zh,
                      const float* __restrict__ Xin,
                      float* __restrict__ Xout, int g) {
    int warp = threadIdx.x >> 5;
    int lane = threadIdx.x & 31;
    int v = blockIdx.x * 8 + warp;
    if (v >= N_ENT) return;

    const uint2* zh2 = (const uint2*)Zh;   // one uint2 = 4 halves = 4 dims
    float sw = g_selfw[g][v];

    uint2 hz = __ldg(&zh2[v * 32 + lane]);
    float2 f0 = __half22float2(*(const __half2*)&hz.x);
    float2 f1 = __half22float2(*(const __half2*)&hz.y);
    float4 acc = make_float4(f0.x * sw, f0.y * sw, f1.x * sw, f1.y * sw);

    const int2* __restrict__ adj = g_adj[g];
    int s = g_off[g][v], e = g_off[g][v + 1];
    int i = s;
    for (; i + 3 < e; i += 4) {
        int2 e0 = __ldg(&adj[i]);
        int2 e1 = __ldg(&adj[i + 1]);
        int2 e2 = __ldg(&adj[i + 2]);
        int2 e3 = __ldg(&adj[i + 3]);
        uint2 h0 = __ldg(&zh2[e0.x * 32 + lane]);
        uint2 h1 = __ldg(&zh2[e1.x * 32 + lane]);
        uint2 h2 = __ldg(&zh2[e2.x * 32 + lane]);
        uint2 h3 = __ldg(&zh2[e3.x * 32 + lane]);
        float w0 = __int_as_float(e0.y), w1 = __int_as_float(e1.y);
        float w2 = __int_as_float(e2.y), w3 = __int_as_float(e3.y);
        {
            float2 a = __half22float2(*(const __half2*)&h0.x);
            float2 b = __half22float2(*(const __half2*)&h0.y);
            acc.x = fmaf(a.x, w0, acc.x); acc.y = fmaf(a.y, w0, acc.y);
            acc.z = fmaf(b.x, w0, acc.z); acc.w = fmaf(b.y, w0, acc.w);
        }
        {
            float2 a = __half22float2(*(const __half2*)&h1.x);
            float2 b = __half22float2(*(const __half2*)&h1.y);
            acc.x = fmaf(a.x, w1, acc.x); acc.y = fmaf(a.y, w1, acc.y);
            acc.z = fmaf(b.x, w1, acc.z); acc.w = fmaf(b.y, w1, acc.w);
        }
        {
            float2 a = __half22float2(*(const __half2*)&h2.x);
            float2 b = __half22float2(*(const __half2*)&h2.y);
            acc.x = fmaf(a.x, w2, acc.x); acc.y = fmaf(a.y, w2, acc.y);
            acc.z = fmaf(b.x, w2, acc.z); acc.w = fmaf(b.y, w2, acc.w);
        }
        {
            float2 a = __half22float2(*(const __half2*)&h3.x);
            float2 b = __half22float2(*(const __half2*)&h3.y);
            acc.x = fmaf(a.x, w3, acc.x); acc.y = fmaf(a.y, w3, acc.y);
            acc.z = fmaf(b.x, w3, acc.z); acc.w = fmaf(b.y, w3, acc.w);
        }
    }
    for (; i < e; i++) {
        int2 e0 = __ldg(&adj[i]);
        float w = __int_as_float(e0.y);
        uint2 h0 = __ldg(&zh2[e0.x * 32 + lane]);
        float2 a = __half22float2(*(const __half2*)&h0.x);
        float2 b = __half22float2(*(const __half2*)&h0.y);
        acc.x = fmaf(a.x, w, acc.x); acc.y = fmaf(a.y, w, acc.y);
        acc.z = fmaf(b.x, w, acc.z); acc.w = fmaf(b.y, w, acc.w);
    }

    float4 xi = __ldg(&((const float4*)Xin)[v * 32 + lane]);
    float4 r;
    r.x = fmaxf(acc.x + xi.x, 0.0f);
    r.y = fmaxf(acc.y + xi.y, 0.0f);
    r.z = fmaxf(acc.z + xi.z, 0.0f);
    r.w = fmaxf(acc.w + xi.w, 0.0f);
    ((float4*)Xout)[v * 32 + lane] = r;
}

// ---------------- seed gather ----------------------------------------------
__global__ void k_gather(const int* __restrict__ seeds,
                         const float* __restrict__ ent,
                         float* __restrict__ out) {
    int i = blockIdx.x * 256 + threadIdx.x;
    if (i < N_SEED * 32) {
        int s = i >> 5, q = i & 31;
        ((float4*)out)[i] = __ldg(&((const float4*)ent)[seeds[s] * 32 + q]);
    }
}

// ---------------- driver (R5-proven topology: 2 streams, inline CSR) --------
static void run_graph(const int* edges, const float* emb,
                      const float* W1, const float* W2,
                      const int* seeds, float* o_ent, float* o_seed,
                      __half* zh, float* x1, int g, cudaStream_t st) {
    const int GB_ENT = (N_ENT + 255) / 256;
    const int GB_EDGE = (N_EDGE + 255) / 256;
    const int NB_SCAN = (N_ENT + 511) / 512;
    const int GEMM_GRID = (N_ENT + 127) / 128;
    const int AGG_GRID  = (N_ENT + 7) / 8;

    k_zero_deg<<<GB_ENT, 256, 0, st>>>(g);
    k_count<<<GB_EDGE, 256, 0, st>>>(edges, g);
    k_scan_a<<<NB_SCAN, 512, 0, st>>>(g);
    k_scan_b<<<1, 256, 0, st>>>(NB_SCAN, g);
    k_scan_c<<<GB_ENT, 256, 0, st>>>(g);
    k_fill<<<GB_EDGE, 256, 0, st>>>(edges, g);

    // layer 1: zh = fp16(emb @ W1) ; x1 = relu(A zh + emb)
    k_gemm<<<GEMM_GRID, 128, 0, st>>>(emb, W1, zh);
    k_agg<<<AGG_GRID, 256, 0, st>>>(zh, emb, x1, g);
    // layer 2: zh = fp16(x1 @ W2) ; ent = relu(A zh + x1)
    k_gemm<<<GEMM_GRID, 128, 0, st>>>(x1, W2, zh);
    k_agg<<<AGG_GRID, 256, 0, st>>>(zh, x1, o_ent, g);

    k_gather<<<(N_SEED * 32 + 255) / 256, 256, 0, st>>>(seeds, o_ent, o_seed);
}

extern "C" void kernel_launch(void* const* d_in, const int* in_sizes, int n_in,
                              void* d_out, int out_size) {
    const int*   sr_seeds = (const int*)d_in[0];
    const int*   tg_seeds = (const int*)d_in[1];
    const float* emb_sr   = (const float*)d_in[4];
    const float* emb_tg   = (const float*)d_in[5];
    const int*   edges_sr = (const int*)d_in[6];
    const int*   edges_tg = (const int*)d_in[7];
    const float* W1       = (const float*)d_in[8];
    const float* W2       = (const float*)d_in[9];

    float* out = (float*)d_out;
    float* o_sr_seed = out;
    float* o_tg_seed = out + (size_t)N_SEED * DIM;
    float* o_sr_ent  = out + (size_t)2 * N_SEED * DIM;
    float* o_tg_ent  = o_sr_ent + (size_t)N_ENT * DIM;

    __half* zhbase; cudaGetSymbolAddress((void**)&zhbase, g_zh);
    float* x1base;  cudaGetSymbolAddress((void**)&x1base, g_x1);

    // one extra stream + fork/join events, created once (outside capture)
    static cudaStream_t s_tg = nullptr;
    static cudaEvent_t ev_fork = nullptr, ev_join = nullptr;
    if (!s_tg) {
        cudaStreamCreateWithFlags(&s_tg, cudaStreamNonBlocking);
        cudaEventCreateWithFlags(&ev_fork, cudaEventDisableTiming);
        cudaEventCreateWithFlags(&ev_join, cudaEventDisableTiming);
    }

    // fork: tg pipeline on side stream, sr pipeline on the capture stream
    cudaEventRecord(ev_fork, 0);
    cudaStreamWaitEvent(s_tg, ev_fork, 0);

    run_graph(edges_sr, emb_sr, W1, W2, sr_seeds, o_sr_ent, o_sr_seed,
              zhbase, x1base, 0, 0);
    run_graph(edges_tg, emb_tg, W1, W2, tg_seeds, o_tg_ent, o_tg_seed,
              zhbase + (size_t)N_ENT * DIM, x1base + (size_t)N_ENT * DIM,
              1, s_tg);

    // join
    cudaEventRecord(ev_join, s_tg);
    cudaStreamWaitEvent(0, ev_join, 0);
}